// round 16
// baseline (speedup 1.0000x reference)
#include <cuda_runtime.h>

// Sparse attention: query l attends to keys l-d, d in
//   {0,1,2,3,4,5,6,7,9,13,21,37,69,133,261,517,1029} (clipped at 0).
// B=4, L=2048, H=8, E=D=64. Layouts [B,L,H,E].
// v9: validated v5 body (2 queries/warp, 9/8 load batches, tree reduction,
//     lane-parallel softmax) wrapped in a PERSISTENT grid-stride loop:
//     grid = 592 CTAs (148 SMs x 4), each warp strides over query pairs.
//     Removes ~6 wave transitions and lets iteration i+1's K loads overlap
//     iteration i's shuffle/softmax phases.

namespace {
constexpr int Lq = 2048;
constexpr int Hh = 8;
constexpr int Ee = 64;
constexpr int NPAIRS = 32768;          // 65536 queries / 2 per warp-iteration
constexpr int NCTA   = 592;            // 148 SMs * 4 resident CTAs
constexpr int WARPS  = NCTA * 8;       // 4736 warps
}

__global__ __launch_bounds__(256, 4) void sparse_attn_kernel(
    const float* __restrict__ Q,
    const float* __restrict__ Kp,
    const float* __restrict__ Vp,
    float*       __restrict__ O)
{
    const unsigned FULL = 0xffffffffu;
    const int offsB[8] = {9,13,21,37,69,133,261,517};

    const int warp   = threadIdx.x >> 5;
    const int lane   = threadIdx.x & 31;
    const int lane16 = lane & 15;
    const int sub    = lane >> 4;
    const int wglob  = blockIdx.x * 8 + warp;

    int my_off;
    {
        const int lo[16] = {0,1,2,3,4,5,6,7,9,13,21,37,69,133,261,517};
        my_off = lo[lane16];
    }

    for (int pr = wglob; pr < NPAIRS; pr += WARPS) {
        const int g  = pr * 2 + sub;

        const int l  = g & (Lq - 1);
        const int bh = g >> 11;
        const int h  = bh & (Hh - 1);
        const int b  = bh >> 3;

        const int rowstride = Hh * Ee;                 // 512 floats
        const int rs4       = rowstride / 4;
        const int base_bh   = b * Lq * rowstride + h * Ee;
        const int qoff      = base_bh + l * rowstride;

        const float4* kbase = reinterpret_cast<const float4*>(Kp + base_bh) + lane16;
        const float4* vbase = reinterpret_cast<const float4*>(Vp + base_bh) + lane16;

        const float4 q = reinterpret_cast<const float4*>(Q + qoff)[lane16];

        float a;      // window half-sum
        float s16;    // offset-1029 score

        // ---- K batch A: offsets 0..7 and 1029 (9 rows) ----
        {
            float4 ka[9];
#pragma unroll
            for (int j = 0; j < 8; ++j) {
                int k = l - j; k = k >= 0 ? k : 0;
                ka[j] = kbase[k * rs4];
            }
            {
                int k = l - 1029; k = k >= 0 ? k : 0;
                ka[8] = kbase[k * rs4];
            }
            float pa[8];
#pragma unroll
            for (int j = 0; j < 8; ++j) {
                float t = q.x * ka[j].x;
                t = fmaf(q.y, ka[j].y, t);
                t = fmaf(q.z, ka[j].z, t);
                pa[j] = fmaf(q.w, ka[j].w, t);
            }
            {
                float t = q.x * ka[8].x;
                t = fmaf(q.y, ka[8].y, t);
                t = fmaf(q.z, ka[8].z, t);
                s16 = fmaf(q.w, ka[8].w, t);
            }
#pragma unroll
            for (int m = 8; m; m >>= 1)
                s16 += __shfl_xor_sync(FULL, s16, m);

            const bool b2 = lane16 & 4;
#pragma unroll
            for (int i = 0; i < 4; ++i) {
                const float send = b2 ? pa[i] : pa[i + 4];
                const float r    = __shfl_xor_sync(FULL, send, 4);
                pa[i] = (b2 ? pa[i + 4] : pa[i]) + r;
            }
            const bool b1 = lane16 & 2;
#pragma unroll
            for (int i = 0; i < 2; ++i) {
                const float send = b1 ? pa[i] : pa[i + 2];
                const float r    = __shfl_xor_sync(FULL, send, 2);
                pa[i] = (b1 ? pa[i + 2] : pa[i]) + r;
            }
            const bool b0 = lane16 & 1;
            const float send = b0 ? pa[0] : pa[1];
            const float r    = __shfl_xor_sync(FULL, send, 1);
            a = (b0 ? pa[1] : pa[0]) + r;
        }

        // ---- K batch B: log offsets (8 rows) ----
        float bb;
        {
            float4 kb[8];
#pragma unroll
            for (int j = 0; j < 8; ++j) {
                int k = l - offsB[j]; k = k >= 0 ? k : 0;
                kb[j] = kbase[k * rs4];
            }
            float pb[8];
#pragma unroll
            for (int j = 0; j < 8; ++j) {
                float t = q.x * kb[j].x;
                t = fmaf(q.y, kb[j].y, t);
                t = fmaf(q.z, kb[j].z, t);
                pb[j] = fmaf(q.w, kb[j].w, t);
            }
            const bool b2 = lane16 & 4;
#pragma unroll
            for (int i = 0; i < 4; ++i) {
                const float send = b2 ? pb[i] : pb[i + 4];
                const float r    = __shfl_xor_sync(FULL, send, 4);
                pb[i] = (b2 ? pb[i + 4] : pb[i]) + r;
            }
            const bool b1 = lane16 & 2;
#pragma unroll
            for (int i = 0; i < 2; ++i) {
                const float send = b1 ? pb[i] : pb[i + 2];
                const float r    = __shfl_xor_sync(FULL, send, 2);
                pb[i] = (b1 ? pb[i + 2] : pb[i]) + r;
            }
            const bool b0 = lane16 & 1;
            const float send = b0 ? pb[0] : pb[1];
            const float r    = __shfl_xor_sync(FULL, send, 1);
            bb = (b0 ? pb[1] : pb[0]) + r;
        }

        // ---- merge halves: lane j (0..15) ends with full score j ----
        float sc;
        {
            const bool hi = lane16 & 8;
            const float send = hi ? a : bb;
            const float r    = __shfl_xor_sync(FULL, send, 8);
            sc = (hi ? bb : a) + r;
        }

        // ---- lane-parallel softmax, no max-subtraction (|s| <~ 6) ----
        float w = (l >= my_off) ? __expf(sc * 0.125f) : 0.f;
        const float w16 = (l >= 1029) ? __expf(s16 * 0.125f) : 0.f;

        float den = w;
#pragma unroll
        for (int m = 8; m; m >>= 1)
            den += __shfl_xor_sync(FULL, den, m);
        den += w16;
        const float inv = __fdividef(1.f, den);

        // ---- V batch 1: offsets 0..7 + offset 9 ----
        float4 acc = make_float4(0.f, 0.f, 0.f, 0.f);
        {
            float4 v1[9];
#pragma unroll
            for (int j = 0; j < 8; ++j) {
                int k = l - j; k = k >= 0 ? k : 0;
                v1[j] = vbase[k * rs4];
            }
            {
                int k = l - 9; k = k >= 0 ? k : 0;
                v1[8] = vbase[k * rs4];
            }
#pragma unroll
            for (int j = 0; j < 9; ++j) {
                const float wj = __shfl_sync(FULL, w, j, 16);
                acc.x = fmaf(wj, v1[j].x, acc.x);
                acc.y = fmaf(wj, v1[j].y, acc.y);
                acc.z = fmaf(wj, v1[j].z, acc.z);
                acc.w = fmaf(wj, v1[j].w, acc.w);
            }
        }
        // ---- V batch 2: log tail (13..517) + 1029 ----
        {
            float4 v2[8];
#pragma unroll
            for (int j = 0; j < 7; ++j) {
                int k = l - offsB[j + 1]; k = k >= 0 ? k : 0;
                v2[j] = vbase[k * rs4];
            }
            {
                int k = l - 1029; k = k >= 0 ? k : 0;
                v2[7] = vbase[k * rs4];
            }
#pragma unroll
            for (int j = 0; j < 7; ++j) {
                const float wj = __shfl_sync(FULL, w, 9 + j, 16);
                acc.x = fmaf(wj, v2[j].x, acc.x);
                acc.y = fmaf(wj, v2[j].y, acc.y);
                acc.z = fmaf(wj, v2[j].z, acc.z);
                acc.w = fmaf(wj, v2[j].w, acc.w);
            }
            acc.x = fmaf(w16, v2[7].x, acc.x);
            acc.y = fmaf(w16, v2[7].y, acc.y);
            acc.z = fmaf(w16, v2[7].z, acc.z);
            acc.w = fmaf(w16, v2[7].w, acc.w);
        }

        float4 out;
        out.x = acc.x * inv;
        out.y = acc.y * inv;
        out.z = acc.z * inv;
        out.w = acc.w * inv;
        reinterpret_cast<float4*>(O + qoff)[lane16] = out;
    }
}

extern "C" void kernel_launch(void* const* d_in, const int* in_sizes, int n_in,
                              void* d_out, int out_size)
{
    const float* Q = (const float*)d_in[0];
    const float* K = (const float*)d_in[1];
    const float* V = (const float*)d_in[2];
    float*       O = (float*)d_out;

    dim3 grid(NCTA);        // persistent: exactly fills 148 SMs x 4 CTAs
    dim3 block(256);
    sparse_attn_kernel<<<grid, block>>>(Q, K, V, O);
}